// round 5
// baseline (speedup 1.0000x reference)
#include <cuda_runtime.h>
#include <cuda_bf16.h>
#include <cstdint>
#include <math.h>

#define BB   64
#define SS   512
#define HID  1024
#define G4   4096
#define ROWS (BB*SS)

// ---------------- device scratch ----------------
__device__ __nv_bfloat16 g_xh[ROWS*HID];
__device__ __nv_bfloat16 g_xl[ROWS*HID];
__device__ __nv_bfloat16 g_wih[(size_t)G4*HID];
__device__ __nv_bfloat16 g_wil[(size_t)G4*HID];
__device__ __nv_bfloat16 g_whh[(size_t)G4*HID];
__device__ __nv_bfloat16 g_whl[(size_t)G4*HID];
__device__ float g_bias[G4];
__device__ float g_xproj[(size_t)SS*BB*G4];
__device__ __nv_bfloat16 g_hh[2][BB*HID];
__device__ __nv_bfloat16 g_hl[2][BB*HID];
__device__ float g_c[BB*HID];

// ---------------- helpers ----------------
__device__ __forceinline__ uint32_t cvta_s(const void* p){
    return (uint32_t)__cvta_generic_to_shared(p);
}
__device__ __forceinline__ uint32_t lds32(uint32_t a){
    uint32_t v; asm volatile("ld.shared.b32 %0,[%1];" : "=r"(v) : "r"(a)); return v;
}
__device__ __forceinline__ void cpa16(uint32_t s, const void* g){
    asm volatile("cp.async.cg.shared.global [%0],[%1],16;" :: "r"(s), "l"(g));
}
#define CP_COMMIT() asm volatile("cp.async.commit_group;")
#define CP_WAIT(N)  asm volatile("cp.async.wait_group %0;" :: "n"(N))

#define MMA_BF16(d, a, b) \
    asm volatile("mma.sync.aligned.m16n8k16.row.col.f32.bf16.bf16.f32 " \
                 "{%0,%1,%2,%3},{%4,%5,%6,%7},{%8,%9},{%0,%1,%2,%3};" \
                 : "+f"(d[0]), "+f"(d[1]), "+f"(d[2]), "+f"(d[3]) \
                 : "r"(a[0]), "r"(a[1]), "r"(a[2]), "r"(a[3]), "r"(b[0]), "r"(b[1]))

__device__ __forceinline__ float sigm(float x){ return 1.f/(1.f + __expf(-x)); }

// ---------------- prep ----------------
__global__ void k_split_x(const float* __restrict__ x){
    int i = blockIdx.x*blockDim.x + threadIdx.x;
    int stride = gridDim.x*blockDim.x;
    for (; i < ROWS*HID; i += stride){
        float v = x[i];
        __nv_bfloat16 h = __float2bfloat16(v);
        g_xh[i] = h;
        g_xl[i] = __float2bfloat16(v - __bfloat162float(h));
    }
}

// transposed + gate-interleaved weights (col = 4*j + gate), hi/lo split
__global__ void k_prep_w(const float* Wii, const float* Wfi, const float* Wgi, const float* Woi,
                         const float* Wih, const float* Wfh, const float* Wgh, const float* Woh,
                         const float* bii, const float* bih, const float* bfi, const float* bfh,
                         const float* bgi, const float* bgh, const float* boi, const float* boh){
    size_t idx = (size_t)blockIdx.x*256 + threadIdx.x;
    if (idx >= (size_t)G4*HID) return;
    int c = (int)(idx >> 10), k = (int)(idx & 1023);
    int j = c >> 2, gg = c & 3;
    const float* wi = (gg==0)?Wii:(gg==1)?Wfi:(gg==2)?Wgi:Woi;
    const float* wh = (gg==0)?Wih:(gg==1)?Wfh:(gg==2)?Wgh:Woh;
    float vi = wi[(size_t)k*HID + j];
    float vh = wh[(size_t)k*HID + j];
    __nv_bfloat16 h1 = __float2bfloat16(vi);
    g_wih[idx] = h1; g_wil[idx] = __float2bfloat16(vi - __bfloat162float(h1));
    __nv_bfloat16 h2 = __float2bfloat16(vh);
    g_whh[idx] = h2; g_whl[idx] = __float2bfloat16(vh - __bfloat162float(h2));
    if (idx < G4){
        int jj = (int)(idx >> 2); int g2 = (int)(idx & 3);
        const float* b1 = (g2==0)?bii:(g2==1)?bfi:(g2==2)?bgi:boi;
        const float* b2 = (g2==0)?bih:(g2==1)?bfh:(g2==2)?bgh:boh;
        g_bias[idx] = b1[jj] + b2[jj];
    }
}

__global__ void k_init(){
    int i = blockIdx.x*256 + threadIdx.x;
    __nv_bfloat16 z = __float2bfloat16(0.f);
    g_hh[0][i] = z; g_hh[1][i] = z;
    g_hl[0][i] = z; g_hl[1][i] = z;
    g_c[i] = 0.f;
}

// ---------------- xproj GEMM [32768,1024]x[1024,4096], 3-term, tile 128x128 ----
#define XP_STAGE 24576
#define RB 48

__global__ void __launch_bounds__(256) k_xproj(){
    extern __shared__ __align__(16) char smem_raw[];
    const uint32_t sbase = cvta_s(smem_raw);
    int tid = threadIdx.x;
    int lane = tid & 31, warp = tid >> 5;
    int g = lane >> 2, tq = lane & 3;
    int wm = warp >> 2, wn = warp & 3;
    int m0 = blockIdx.y * 128, n0 = blockIdx.x * 128;

    auto stage_load = [&](int kt, int s){
        int arr = tid >> 7, rem = tid & 127;
        int chunk = rem & 1, rc = rem >> 1;
        const __nv_bfloat16* gA = arr ? g_xl : g_xh;
        const __nv_bfloat16* gB = arr ? g_wil : g_wih;
        uint32_t aA = sbase + s*XP_STAGE + arr*6144;
        uint32_t aB = sbase + s*XP_STAGE + 12288 + arr*6144;
        #pragma unroll
        for (int i = 0; i < 2; i++){
            int row = rc + i*64;
            cpa16(aA + row*RB + chunk*16, gA + (size_t)(m0+row)*HID + kt*16 + chunk*8);
            cpa16(aB + row*RB + chunk*16, gB + (size_t)(n0+row)*HID + kt*16 + chunk*8);
        }
        CP_COMMIT();
    };

    stage_load(0, 0);
    stage_load(1, 1);

    float acc[4][4][4];
    #pragma unroll
    for (int ma = 0; ma < 4; ma++)
        #pragma unroll
        for (int na = 0; na < 4; na++){
            int c = n0 + wn*32 + na*8 + 2*tq;
            float b0 = g_bias[c], b1 = g_bias[c+1];
            acc[ma][na][0] = b0; acc[ma][na][1] = b1;
            acc[ma][na][2] = b0; acc[ma][na][3] = b1;
        }

    for (int kt = 0; kt < 64; kt++){
        CP_WAIT(1);
        __syncthreads();
        if (kt + 2 < 64) stage_load(kt + 2, (kt + 2) % 3);
        else CP_COMMIT();

        uint32_t st = sbase + (kt % 3)*XP_STAGE;
        uint32_t Ah = st, Al = st + 6144, Bh = st + 12288, Bl = st + 18432;
        uint32_t ah[4][4], al[4][4], bh[4][2], bl[4][2];
        #pragma unroll
        for (int ma = 0; ma < 4; ma++){
            int r = wm*64 + ma*16 + g;
            uint32_t o0 = r*RB + tq*4, o1 = (r+8)*RB + tq*4;
            ah[ma][0] = lds32(Ah + o0);      ah[ma][1] = lds32(Ah + o1);
            ah[ma][2] = lds32(Ah + o0 + 16); ah[ma][3] = lds32(Ah + o1 + 16);
            al[ma][0] = lds32(Al + o0);      al[ma][1] = lds32(Al + o1);
            al[ma][2] = lds32(Al + o0 + 16); al[ma][3] = lds32(Al + o1 + 16);
        }
        #pragma unroll
        for (int na = 0; na < 4; na++){
            int cb = wn*32 + na*8 + g;
            uint32_t o = cb*RB + tq*4;
            bh[na][0] = lds32(Bh + o); bh[na][1] = lds32(Bh + o + 16);
            bl[na][0] = lds32(Bl + o); bl[na][1] = lds32(Bl + o + 16);
        }
        #pragma unroll
        for (int ma = 0; ma < 4; ma++)
            #pragma unroll
            for (int na = 0; na < 4; na++){
                MMA_BF16(acc[ma][na], ah[ma], bh[na]);
                MMA_BF16(acc[ma][na], ah[ma], bl[na]);
                MMA_BF16(acc[ma][na], al[ma], bh[na]);
            }
    }

    CP_WAIT(0);
    __syncthreads();
    float* sOut = (float*)smem_raw;  // 128 x 132
    #pragma unroll
    for (int ma = 0; ma < 4; ma++)
        #pragma unroll
        for (int na = 0; na < 4; na++){
            int r = wm*64 + ma*16 + g;
            int c = wn*32 + na*8 + 2*tq;
            sOut[r*132 + c]       = acc[ma][na][0];
            sOut[r*132 + c + 1]   = acc[ma][na][1];
            sOut[(r+8)*132 + c]   = acc[ma][na][2];
            sOut[(r+8)*132 + c+1] = acc[ma][na][3];
        }
    __syncthreads();
    #pragma unroll
    for (int it = 0; it < 16; it++){
        int r2 = (tid >> 5) + it*8;
        int rg = m0 + r2;
        int b = rg >> 9, s = rg & 511;
        float4 v = *(float4*)(sOut + r2*132 + lane*4);
        *(float4*)(g_xproj + ((size_t)(s*64 + b))*G4 + n0 + lane*4) = v;
    }
}

// ---------------- fused recurrent step: M=64(batch) x N=32, 128 CTAs --------
// Stage layout (9216 B): Ah[0,3072) Al[3072,6144) Bh[6144,7680) Bl[7680,9216)
#define ST_STAGE 9216
#define ST_SG 36864             // 4 stages

__global__ void __launch_bounds__(256) k_step(int t, float* __restrict__ out){
    extern __shared__ __align__(16) char smem_raw[];
    const uint32_t sbase = cvta_s(smem_raw);
    float* sG = (float*)(smem_raw + ST_SG);   // 64 x 36 floats
    int tid = threadIdx.x;
    int lane = tid & 31, warp = tid >> 5;
    int g = lane >> 2, tq = lane & 3;
    int wm = warp & 1, wn = warp >> 1;        // 2 x 4
    int n0 = blockIdx.x * 32;
    const __nv_bfloat16* hinH = g_hh[t & 1];
    const __nv_bfloat16* hinL = g_hl[t & 1];
    __nv_bfloat16* houtH = g_hh[(t + 1) & 1];
    __nv_bfloat16* houtL = g_hl[(t + 1) & 1];

    auto stage_load = [&](int kt, int s){
        int arr = tid >> 7, rem = tid & 127;    // 128 thr per hi/lo half
        uint32_t stb = sbase + s*ST_STAGE;
        if (rem < 64){                          // A: 64 rows of h, 32B/row
            int chunk = rem & 1, rc = rem >> 1; // rc 0..31
            #pragma unroll
            for (int i = 0; i < 2; i++){
                int row = rc + i*32;
                cpa16(stb + arr*3072 + row*RB + chunk*16,
                      (arr ? hinL : hinH) + (size_t)row*HID + kt*16 + chunk*8);
            }
        } else {                                // B: 32 rows of Wh^T, 1536B each
            int r2 = rem - 64;
            int chunk = r2 & 1, rc = r2 >> 1;   // rc 0..31
            cpa16(stb + 6144 + arr*1536 + rc*RB + chunk*16,
                  (arr ? g_whl : g_whh) + (size_t)(n0+rc)*HID + kt*16 + chunk*8);
        }
        CP_COMMIT();
    };

    stage_load(0, 0); stage_load(1, 1); stage_load(2, 2);

    float acc[2][4];
    #pragma unroll
    for (int ma = 0; ma < 2; ma++){
        int r = wm*32 + ma*16 + g;
        int c = n0 + wn*8 + 2*tq;
        const float* xp  = g_xproj + ((size_t)t*BB + r)*G4 + c;
        const float* xp2 = g_xproj + ((size_t)t*BB + r + 8)*G4 + c;
        acc[ma][0] = xp[0];  acc[ma][1] = xp[1];
        acc[ma][2] = xp2[0]; acc[ma][3] = xp2[1];
    }

    for (int kt = 0; kt < 64; kt++){
        CP_WAIT(2);
        __syncthreads();
        if (kt + 3 < 64) stage_load(kt + 3, (kt + 3) & 3);
        else CP_COMMIT();

        uint32_t st = sbase + (kt & 3)*ST_STAGE;
        uint32_t Ah = st, Al = st + 3072, Bh = st + 6144, Bl = st + 7680;
        uint32_t ah[2][4], al[2][4], bh[2], bl[2];
        #pragma unroll
        for (int ma = 0; ma < 2; ma++){
            int r = wm*32 + ma*16 + g;
            uint32_t o0 = r*RB + tq*4, o1 = (r+8)*RB + tq*4;
            ah[ma][0] = lds32(Ah + o0);      ah[ma][1] = lds32(Ah + o1);
            ah[ma][2] = lds32(Ah + o0 + 16); ah[ma][3] = lds32(Ah + o1 + 16);
            al[ma][0] = lds32(Al + o0);      al[ma][1] = lds32(Al + o1);
            al[ma][2] = lds32(Al + o0 + 16); al[ma][3] = lds32(Al + o1 + 16);
        }
        {
            int cb = wn*8 + g;
            uint32_t o = cb*RB + tq*4;
            bh[0] = lds32(Bh + o); bh[1] = lds32(Bh + o + 16);
            bl[0] = lds32(Bl + o); bl[1] = lds32(Bl + o + 16);
        }
        #pragma unroll
        for (int ma = 0; ma < 2; ma++){
            MMA_BF16(acc[ma], ah[ma], bh);
            MMA_BF16(acc[ma], ah[ma], bl);
            MMA_BF16(acc[ma], al[ma], bh);
        }
    }

    #pragma unroll
    for (int ma = 0; ma < 2; ma++){
        int r = wm*32 + ma*16 + g;
        int c = wn*8 + 2*tq;
        sG[r*36 + c]       = acc[ma][0];
        sG[r*36 + c + 1]   = acc[ma][1];
        sG[(r+8)*36 + c]   = acc[ma][2];
        sG[(r+8)*36 + c+1] = acc[ma][3];
    }
    __syncthreads();

    // cell update: h-units j = n0/4 .. +7, 64 batches
    bool last = (t == SS - 1);
    #pragma unroll
    for (int p = 0; p < 2; p++){
        int pair = p*256 + tid;            // 0..511
        int b = pair >> 3, jl = pair & 7;
        float4 gt = *(float4*)(sG + b*36 + jl*4);
        float iv = sigm(gt.x);
        float fv = sigm(gt.y);
        float gv = tanhf(gt.z);
        float ov = sigm(gt.w);
        int ci = b*HID + (n0 >> 2) + jl;
        float cn = fv * g_c[ci] + iv * gv;
        g_c[ci] = cn;
        float h = ov * tanhf(cn);
        __nv_bfloat16 hh = __float2bfloat16(h);
        houtH[ci] = hh;
        houtL[ci] = __float2bfloat16(h - __bfloat162float(hh));
        if (last){ out[ci] = h; out[BB*HID + ci] = cn; }
    }
}

// ---------------- launch ----------------
extern "C" void kernel_launch(void* const* d_in, const int* in_sizes, int n_in,
                              void* d_out, int out_size){
    // dict order: x, Wii,Wfi,Wgi,Woi, Wih,Wfh,Wgh,Woh, bii,bih,bfi,bfh,bgi,bgh,boi,boh
    const float* x = nullptr;
    const float* w[8] = {nullptr}; const float* bp[8] = {nullptr};
    int nw = 0, nb = 0;
    for (int i = 0; i < n_in; i++){
        if (in_sizes[i] == ROWS*HID)      x = (const float*)d_in[i];
        else if (in_sizes[i] == HID*HID){ if (nw < 8) w[nw++] = (const float*)d_in[i]; }
        else if (in_sizes[i] == HID){     if (nb < 8) bp[nb++] = (const float*)d_in[i]; }
    }
    float* out = (float*)d_out;

    cudaFuncSetAttribute(k_xproj, cudaFuncAttributeMaxDynamicSharedMemorySize, 3*XP_STAGE);
    cudaFuncSetAttribute(k_step,  cudaFuncAttributeMaxDynamicSharedMemorySize, ST_SG + 64*36*4);

    k_split_x<<<2048, 256>>>(x);
    k_prep_w<<<16384, 256>>>(w[0], w[1], w[2], w[3], w[4], w[5], w[6], w[7],
                             bp[0], bp[1], bp[2], bp[3], bp[4], bp[5], bp[6], bp[7]);
    k_init<<<256, 256>>>();
    dim3 gx(32, 256);
    k_xproj<<<gx, 256, 3*XP_STAGE>>>();
    for (int t = 0; t < SS; t++)
        k_step<<<128, 256, ST_SG + 64*36*4>>>(t, out);
}

// round 7
// speedup vs baseline: 1.2582x; 1.2582x over previous
#include <cuda_runtime.h>
#include <cuda_bf16.h>
#include <cstdint>
#include <math.h>

#define BB   64
#define SS   512
#define HID  1024
#define G4   4096
#define ROWS (BB*SS)
#define NCTA 128

// ---------------- device scratch ----------------
__device__ __nv_bfloat16 g_xh[ROWS*HID];
__device__ __nv_bfloat16 g_xl[ROWS*HID];
__device__ __nv_bfloat16 g_wih[(size_t)G4*HID];
__device__ __nv_bfloat16 g_wil[(size_t)G4*HID];
__device__ __nv_bfloat16 g_whh[(size_t)G4*HID];
__device__ __nv_bfloat16 g_whl[(size_t)G4*HID];
__device__ float g_bias[G4];
__device__ float g_xproj[(size_t)SS*BB*G4];
__device__ __nv_bfloat16 g_hh[2][BB*HID];
__device__ __nv_bfloat16 g_hl[2][BB*HID];
__device__ float g_c[BB*HID];
__device__ unsigned g_count;

// ---------------- helpers ----------------
__device__ __forceinline__ uint32_t cvta_s(const void* p){
    return (uint32_t)__cvta_generic_to_shared(p);
}
__device__ __forceinline__ uint32_t lds32(uint32_t a){
    uint32_t v; asm volatile("ld.shared.b32 %0,[%1];" : "=r"(v) : "r"(a)); return v;
}
__device__ __forceinline__ void cpa16(uint32_t s, const void* g){
    asm volatile("cp.async.cg.shared.global [%0],[%1],16;" :: "r"(s), "l"(g));
}
#define CP_COMMIT() asm volatile("cp.async.commit_group;")
#define CP_WAIT(N)  asm volatile("cp.async.wait_group %0;" :: "n"(N))

#define MMA_BF16(d, a, b) \
    asm volatile("mma.sync.aligned.m16n8k16.row.col.f32.bf16.bf16.f32 " \
                 "{%0,%1,%2,%3},{%4,%5,%6,%7},{%8,%9},{%0,%1,%2,%3};" \
                 : "+f"(d[0]), "+f"(d[1]), "+f"(d[2]), "+f"(d[3]) \
                 : "r"(a[0]), "r"(a[1]), "r"(a[2]), "r"(a[3]), "r"(b[0]), "r"(b[1]))

__device__ __forceinline__ float sigm(float x){ return 1.f/(1.f + __expf(-x)); }

// ---------------- prep ----------------
__global__ void k_split_x(const float* __restrict__ x){
    int i = blockIdx.x*blockDim.x + threadIdx.x;
    int stride = gridDim.x*blockDim.x;
    for (; i < ROWS*HID; i += stride){
        float v = x[i];
        __nv_bfloat16 h = __float2bfloat16(v);
        g_xh[i] = h;
        g_xl[i] = __float2bfloat16(v - __bfloat162float(h));
    }
}

// transposed + gate-interleaved weights (col = 4*j + gate), hi/lo split
__global__ void k_prep_w(const float* Wii, const float* Wfi, const float* Wgi, const float* Woi,
                         const float* Wih, const float* Wfh, const float* Wgh, const float* Woh,
                         const float* bii, const float* bih, const float* bfi, const float* bfh,
                         const float* bgi, const float* bgh, const float* boi, const float* boh){
    size_t idx = (size_t)blockIdx.x*256 + threadIdx.x;
    if (idx >= (size_t)G4*HID) return;
    int c = (int)(idx >> 10), k = (int)(idx & 1023);
    int j = c >> 2, gg = c & 3;
    const float* wi = (gg==0)?Wii:(gg==1)?Wfi:(gg==2)?Wgi:Woi;
    const float* wh = (gg==0)?Wih:(gg==1)?Wfh:(gg==2)?Wgh:Woh;
    float vi = wi[(size_t)k*HID + j];
    float vh = wh[(size_t)k*HID + j];
    __nv_bfloat16 h1 = __float2bfloat16(vi);
    g_wih[idx] = h1; g_wil[idx] = __float2bfloat16(vi - __bfloat162float(h1));
    __nv_bfloat16 h2 = __float2bfloat16(vh);
    g_whh[idx] = h2; g_whl[idx] = __float2bfloat16(vh - __bfloat162float(h2));
    if (idx < G4){
        int jj = (int)(idx >> 2); int g2 = (int)(idx & 3);
        const float* b1 = (g2==0)?bii:(g2==1)?bfi:(g2==2)?bgi:boi;
        const float* b2 = (g2==0)?bih:(g2==1)?bfh:(g2==2)?bgh:boh;
        g_bias[idx] = b1[jj] + b2[jj];
    }
}

__global__ void k_init(){
    int i = blockIdx.x*256 + threadIdx.x;
    __nv_bfloat16 z = __float2bfloat16(0.f);
    g_hh[0][i] = z; g_hh[1][i] = z;
    g_hl[0][i] = z; g_hl[1][i] = z;
    g_c[i] = 0.f;
    if (i == 0) g_count = 0u;
}

// ---------------- xproj GEMM [32768,1024]x[1024,4096], 3-term, tile 128x128 ----
#define XP_STAGE 24576
#define RB 48

__global__ void __launch_bounds__(256) k_xproj(){
    extern __shared__ __align__(16) char smem_raw[];
    const uint32_t sbase = cvta_s(smem_raw);
    int tid = threadIdx.x;
    int lane = tid & 31, warp = tid >> 5;
    int g = lane >> 2, tq = lane & 3;
    int wm = warp >> 2, wn = warp & 3;
    int m0 = blockIdx.y * 128, n0 = blockIdx.x * 128;

    auto stage_load = [&](int kt, int s){
        int arr = tid >> 7, rem = tid & 127;
        int chunk = rem & 1, rc = rem >> 1;
        const __nv_bfloat16* gA = arr ? g_xl : g_xh;
        const __nv_bfloat16* gB = arr ? g_wil : g_wih;
        uint32_t aA = sbase + s*XP_STAGE + arr*6144;
        uint32_t aB = sbase + s*XP_STAGE + 12288 + arr*6144;
        #pragma unroll
        for (int i = 0; i < 2; i++){
            int row = rc + i*64;
            cpa16(aA + row*RB + chunk*16, gA + (size_t)(m0+row)*HID + kt*16 + chunk*8);
            cpa16(aB + row*RB + chunk*16, gB + (size_t)(n0+row)*HID + kt*16 + chunk*8);
        }
        CP_COMMIT();
    };

    stage_load(0, 0);
    stage_load(1, 1);

    float acc[4][4][4];
    #pragma unroll
    for (int ma = 0; ma < 4; ma++)
        #pragma unroll
        for (int na = 0; na < 4; na++){
            int c = n0 + wn*32 + na*8 + 2*tq;
            float b0 = g_bias[c], b1 = g_bias[c+1];
            acc[ma][na][0] = b0; acc[ma][na][1] = b1;
            acc[ma][na][2] = b0; acc[ma][na][3] = b1;
        }

    for (int kt = 0; kt < 64; kt++){
        CP_WAIT(1);
        __syncthreads();
        if (kt + 2 < 64) stage_load(kt + 2, (kt + 2) % 3);
        else CP_COMMIT();

        uint32_t st = sbase + (kt % 3)*XP_STAGE;
        uint32_t Ah = st, Al = st + 6144, Bh = st + 12288, Bl = st + 18432;
        uint32_t ah[4][4], al[4][4], bh[4][2], bl[4][2];
        #pragma unroll
        for (int ma = 0; ma < 4; ma++){
            int r = wm*64 + ma*16 + g;
            uint32_t o0 = r*RB + tq*4, o1 = (r+8)*RB + tq*4;
            ah[ma][0] = lds32(Ah + o0);      ah[ma][1] = lds32(Ah + o1);
            ah[ma][2] = lds32(Ah + o0 + 16); ah[ma][3] = lds32(Ah + o1 + 16);
            al[ma][0] = lds32(Al + o0);      al[ma][1] = lds32(Al + o1);
            al[ma][2] = lds32(Al + o0 + 16); al[ma][3] = lds32(Al + o1 + 16);
        }
        #pragma unroll
        for (int na = 0; na < 4; na++){
            int cb = wn*32 + na*8 + g;
            uint32_t o = cb*RB + tq*4;
            bh[na][0] = lds32(Bh + o); bh[na][1] = lds32(Bh + o + 16);
            bl[na][0] = lds32(Bl + o); bl[na][1] = lds32(Bl + o + 16);
        }
        #pragma unroll
        for (int ma = 0; ma < 4; ma++)
            #pragma unroll
            for (int na = 0; na < 4; na++){
                MMA_BF16(acc[ma][na], ah[ma], bh[na]);
                MMA_BF16(acc[ma][na], ah[ma], bl[na]);
                MMA_BF16(acc[ma][na], al[ma], bh[na]);
            }
    }

    CP_WAIT(0);
    __syncthreads();
    float* sOut = (float*)smem_raw;  // 128 x 132
    #pragma unroll
    for (int ma = 0; ma < 4; ma++)
        #pragma unroll
        for (int na = 0; na < 4; na++){
            int r = wm*64 + ma*16 + g;
            int c = wn*32 + na*8 + 2*tq;
            sOut[r*132 + c]       = acc[ma][na][0];
            sOut[r*132 + c + 1]   = acc[ma][na][1];
            sOut[(r+8)*132 + c]   = acc[ma][na][2];
            sOut[(r+8)*132 + c+1] = acc[ma][na][3];
        }
    __syncthreads();
    #pragma unroll
    for (int it = 0; it < 16; it++){
        int r2 = (tid >> 5) + it*8;
        int rg = m0 + r2;
        int b = rg >> 9, s = rg & 511;
        float4 v = *(float4*)(sOut + r2*132 + lane*4);
        *(float4*)(g_xproj + ((size_t)(s*64 + b))*G4 + n0 + lane*4) = v;
    }
}

// ---------------- persistent recurrence: 128 CTAs, all 512 steps ----------------
// SMEM map (bytes):
//   [0, 81920)        B-hi resident: 64 kt-tiles x 32 rows x 40 B
//   [81920, 163840)   B-lo resident (same layout)
//   [163840, 188416)  A stream: 4 stages x 6144 (Ah 3072 + Al 3072, 64 rows x 48 B)
//   [188416, 197632)  sG gate buffer: 64 x 36 floats
#define R_BLO   81920
#define R_ABASE 163840
#define R_ASTG  6144
#define R_SG    188416
#define R_SMEM  197632

__global__ void __launch_bounds__(256, 1) k_recur(float* __restrict__ out){
    extern __shared__ __align__(16) char smem_raw[];
    const uint32_t sbase = cvta_s(smem_raw);
    uint32_t* s32 = (uint32_t*)smem_raw;
    float* sG = (float*)(smem_raw + R_SG);
    int tid = threadIdx.x;
    int lane = tid & 31, warp = tid >> 5;
    int g = lane >> 2, tq = lane & 3;
    int wm = warp & 1, wn = warp >> 1;       // 2 x 4 warps
    int n0 = blockIdx.x * 32;

    // ---- load resident Wh slice (rows n0..n0+31), hi+lo, once ----
    for (int i = tid; i < 64*32*8; i += 256){         // 16384 words per array
        int w4 = i & 7, row = (i >> 3) & 31, kt = i >> 8;
        uint32_t off = (uint32_t)kt*1280u + (uint32_t)row*40u + (uint32_t)w4*4u;
        const uint32_t* srcH = (const uint32_t*)(g_whh + (size_t)(n0+row)*HID + kt*16);
        const uint32_t* srcL = (const uint32_t*)(g_whl + (size_t)(n0+row)*HID + kt*16);
        s32[off >> 2]              = srcH[w4];
        s32[(off + R_BLO) >> 2]    = srcL[w4];
    }
    __syncthreads();

    for (int t = 0; t < SS; t++){
        const __nv_bfloat16* hinH = g_hh[t & 1];
        const __nv_bfloat16* hinL = g_hl[t & 1];
        __nv_bfloat16* houtH = g_hh[(t + 1) & 1];
        __nv_bfloat16* houtL = g_hl[(t + 1) & 1];

        auto stage_load = [&](int kt, int s){
            int arr = tid >> 7, rem = tid & 127;       // 128 thr per hi/lo half
            int chunk = rem & 1, rc = rem >> 1;        // rc 0..63 rows
            cpa16(sbase + R_ABASE + s*R_ASTG + arr*3072 + rc*RB + chunk*16,
                  (arr ? hinL : hinH) + (size_t)rc*HID + kt*16 + chunk*8);
            CP_COMMIT();
        };

        stage_load(0, 0); stage_load(1, 1); stage_load(2, 2);

        float acc[2][4];
        #pragma unroll
        for (int ma = 0; ma < 2; ma++){
            int r = wm*32 + ma*16 + g;
            int c = n0 + wn*8 + 2*tq;
            const float* xp  = g_xproj + ((size_t)t*BB + r)*G4 + c;
            const float* xp2 = g_xproj + ((size_t)t*BB + r + 8)*G4 + c;
            acc[ma][0] = xp[0];  acc[ma][1] = xp[1];
            acc[ma][2] = xp2[0]; acc[ma][3] = xp2[1];
        }

        for (int kt = 0; kt < 64; kt++){
            CP_WAIT(2);
            __syncthreads();
            if (kt + 3 < 64) stage_load(kt + 3, (kt + 3) & 3);
            else CP_COMMIT();

            uint32_t st = sbase + R_ABASE + (kt & 3)*R_ASTG;
            uint32_t Ah = st, Al = st + 3072;
            uint32_t Bh = sbase + (uint32_t)kt*1280u;
            uint32_t Bl = Bh + R_BLO;
            uint32_t ah[2][4], al[2][4], bh[2], bl[2];
            #pragma unroll
            for (int ma = 0; ma < 2; ma++){
                int r = wm*32 + ma*16 + g;
                uint32_t o0 = r*RB + tq*4, o1 = (r+8)*RB + tq*4;
                ah[ma][0] = lds32(Ah + o0);      ah[ma][1] = lds32(Ah + o1);
                ah[ma][2] = lds32(Ah + o0 + 16); ah[ma][3] = lds32(Ah + o1 + 16);
                al[ma][0] = lds32(Al + o0);      al[ma][1] = lds32(Al + o1);
                al[ma][2] = lds32(Al + o0 + 16); al[ma][3] = lds32(Al + o1 + 16);
            }
            {
                int cb = wn*8 + g;
                uint32_t o = cb*40 + tq*4;
                bh[0] = lds32(Bh + o); bh[1] = lds32(Bh + o + 16);
                bl[0] = lds32(Bl + o); bl[1] = lds32(Bl + o + 16);
            }
            #pragma unroll
            for (int ma = 0; ma < 2; ma++){
                MMA_BF16(acc[ma], ah[ma], bh);
                MMA_BF16(acc[ma], ah[ma], bl);
                MMA_BF16(acc[ma], al[ma], bh);
            }
        }

        #pragma unroll
        for (int ma = 0; ma < 2; ma++){
            int r = wm*32 + ma*16 + g;
            int c = wn*8 + 2*tq;
            sG[r*36 + c]       = acc[ma][0];
            sG[r*36 + c + 1]   = acc[ma][1];
            sG[(r+8)*36 + c]   = acc[ma][2];
            sG[(r+8)*36 + c+1] = acc[ma][3];
        }
        __syncthreads();

        // cell update: h-units j = n0/4 .. +7, 64 batches
        bool last = (t == SS - 1);
        #pragma unroll
        for (int p = 0; p < 2; p++){
            int pair = p*256 + tid;            // 0..511
            int b = pair >> 3, jl = pair & 7;
            float4 gt = *(float4*)(sG + b*36 + jl*4);
            float iv = sigm(gt.x);
            float fv = sigm(gt.y);
            float gv = tanhf(gt.z);
            float ov = sigm(gt.w);
            int ci = b*HID + (n0 >> 2) + jl;
            float cn = fv * g_c[ci] + iv * gv;
            g_c[ci] = cn;
            float h = ov * tanhf(cn);
            __nv_bfloat16 hh = __float2bfloat16(h);
            float hlf = h - __bfloat162float(hh);
            __nv_bfloat16 hl = __float2bfloat16(hlf);
            asm volatile("st.global.cg.u16 [%0], %1;" :: "l"(houtH + ci),
                         "h"(*(const unsigned short*)&hh));
            asm volatile("st.global.cg.u16 [%0], %1;" :: "l"(houtL + ci),
                         "h"(*(const unsigned short*)&hl));
            if (last){ out[ci] = h; out[BB*HID + ci] = cn; }
        }
        __syncthreads();

        // ---- grid barrier (monotonic counter, all 128 CTAs co-resident) ----
        if (tid == 0){
            __threadfence();
            atomicAdd(&g_count, 1u);
            unsigned target = (unsigned)NCTA * (unsigned)(t + 1);
            unsigned v;
            do {
                asm volatile("ld.global.acquire.gpu.u32 %0,[%1];"
                             : "=r"(v) : "l"(&g_count));
            } while (v < target);
        }
        __syncthreads();
    }
}

// ---------------- launch ----------------
extern "C" void kernel_launch(void* const* d_in, const int* in_sizes, int n_in,
                              void* d_out, int out_size){
    // dict order: x, Wii,Wfi,Wgi,Woi, Wih,Wfh,Wgh,Woh, bii,bih,bfi,bfh,bgi,bgh,boi,boh
    const float* x = nullptr;
    const float* w[8] = {nullptr}; const float* bp[8] = {nullptr};
    int nw = 0, nb = 0;
    for (int i = 0; i < n_in; i++){
        if (in_sizes[i] == ROWS*HID)      x = (const float*)d_in[i];
        else if (in_sizes[i] == HID*HID){ if (nw < 8) w[nw++] = (const float*)d_in[i]; }
        else if (in_sizes[i] == HID){     if (nb < 8) bp[nb++] = (const float*)d_in[i]; }
    }
    float* out = (float*)d_out;

    cudaFuncSetAttribute(k_xproj, cudaFuncAttributeMaxDynamicSharedMemorySize, 3*XP_STAGE);
    cudaFuncSetAttribute(k_recur, cudaFuncAttributeMaxDynamicSharedMemorySize, R_SMEM);

    k_split_x<<<2048, 256>>>(x);
    k_prep_w<<<16384, 256>>>(w[0], w[1], w[2], w[3], w[4], w[5], w[6], w[7],
                             bp[0], bp[1], bp[2], bp[3], bp[4], bp[5], bp[6], bp[7]);
    k_init<<<256, 256>>>();
    dim3 gx(32, 256);
    k_xproj<<<gx, 256, 3*XP_STAGE>>>();
    k_recur<<<NCTA, 256, R_SMEM>>>(out);
}